// round 17
// baseline (speedup 1.0000x reference)
#include <cuda_runtime.h>
#include <cuda_bf16.h>
#include <cstdint>

#define B_    256
#define T_    512
#define IN_   64
#define H_    1024
#define OUT_  128
#define NCTA  128
#define NTHR  512
#define HBUF  (16 * 64 * 2 * 32)      // uint4s per h buffer: [mt][kc][hl][lane]
#define B_BYTES   139264              // 68 kc x 2048 B (frag-pair interleaved, hi|lo)
#define EXCH_OFF  B_BYTES             // 4 wk-partials x (4 wm x 2048 B)
#define SMEM_BYTES (B_BYTES + 4 * 8192)

// ---------------- persistent device scratch ------------------------------
__device__ uint4 g_hA[2 * HBUF];                     // ping-pong h, A-frag packed
__device__ uint4 g_xp[(size_t)T_ * 16 * 4 * 2 * 32]; // x, A-frag packed per t
__device__ float g_hf[B_ * H_];                      // final h, plain fp32
__device__ unsigned g_bar_count;                     // one-time init barrier
__device__ volatile unsigned g_bar_gen;
// per-m-group step barriers, each counter/gen on its own 128B line
__device__ __align__(128) unsigned g_gcnt[4 * 32];
__device__ __align__(128) volatile unsigned g_ggen[4 * 32];

// ---------------- helpers -------------------------------------------------
__device__ __forceinline__ uint32_t smem_u32(const void* p) {
    uint32_t a;
    asm("{ .reg .u64 t; cvta.to.shared.u64 t, %1; cvt.u32.u64 %0, t; }"
        : "=r"(a) : "l"(p));
    return a;
}

__device__ __forceinline__ uint32_t pk(float a, float b) {
    __nv_bfloat162 t = __floats2bfloat162_rn(a, b);
    return *reinterpret_cast<uint32_t*>(&t);
}

__device__ __forceinline__ void lds128(uint32_t* r, uint32_t a) {
    asm("ld.shared.v4.b32 {%0,%1,%2,%3}, [%4];"
        : "=r"(r[0]), "=r"(r[1]), "=r"(r[2]), "=r"(r[3]) : "r"(a));
}

__device__ __forceinline__ void mma16816(float* c, const uint32_t* a, const uint32_t* b) {
    asm("mma.sync.aligned.m16n8k16.row.col.f32.bf16.bf16.f32 "
        "{%0,%1,%2,%3}, {%4,%5,%6,%7}, {%8,%9}, {%0,%1,%2,%3};"
        : "+f"(c[0]), "+f"(c[1]), "+f"(c[2]), "+f"(c[3])
        : "r"(a[0]), "r"(a[1]), "r"(a[2]), "r"(a[3]), "r"(b[0]), "r"(b[1]));
}

// one-time full-grid barrier (init only)
__device__ __forceinline__ void grid_sync_all() {
    __syncthreads();
    if (threadIdx.x == 0) {
        __threadfence();
        unsigned gen = g_bar_gen;
        if (atomicAdd(&g_bar_count, 1u) == NCTA - 1u) {
            atomicExch(&g_bar_count, 0u);
            __threadfence();
            g_bar_gen = gen + 1u;
        } else {
            while (g_bar_gen == gen) { }
        }
        __threadfence();
    }
    __syncthreads();
}

// per-step barrier over the 32 CTAs of one m-group
__device__ __forceinline__ void group_sync(int g) {
    __syncthreads();
    if (threadIdx.x == 0) {
        __threadfence();
        const int s = g * 32;
        unsigned gen = g_ggen[s];
        if (atomicAdd(&g_gcnt[s], 1u) == 31u) {
            atomicExch(&g_gcnt[s], 0u);
            __threadfence();
            g_ggen[s] = gen + 1u;
        } else {
            while (g_ggen[s] == gen) { }
        }
        __threadfence();
    }
    __syncthreads();
}

// ---------------- pack x into A-fragment layout (one-time) ----------------
__global__ void pack_x(const float* __restrict__ x, uint4* __restrict__ xp) {
    int id = blockIdx.x * (blockDim.x >> 5) + (threadIdx.x >> 5);
    int l  = threadIdx.x & 31;
    if (id >= T_ * 16 * 4) return;
    int t = id >> 6, mt = (id >> 2) & 15, kcx = id & 3;
    int b0 = mt * 16 + (l >> 2), b1 = b0 + 8;
    int i0 = kcx * 16 + 2 * (l & 3);
    const float* x0 = x + ((size_t)b0 * T_ + t) * IN_;
    const float* x1 = x + ((size_t)b1 * T_ + t) * IN_;
    float v00 = x0[i0], v01 = x0[i0 + 1], v02 = x0[i0 + 8], v03 = x0[i0 + 9];
    float v10 = x1[i0], v11 = x1[i0 + 1], v12 = x1[i0 + 8], v13 = x1[i0 + 9];
    uint4 hi4, lo4;
    hi4.x = pk(v00, v01); hi4.y = pk(v10, v11);
    hi4.z = pk(v02, v03); hi4.w = pk(v12, v13);
    float r00 = v00 - __bfloat162float(__float2bfloat16(v00));
    float r01 = v01 - __bfloat162float(__float2bfloat16(v01));
    float r02 = v02 - __bfloat162float(__float2bfloat16(v02));
    float r03 = v03 - __bfloat162float(__float2bfloat16(v03));
    float r10 = v10 - __bfloat162float(__float2bfloat16(v10));
    float r11 = v11 - __bfloat162float(__float2bfloat16(v11));
    float r12 = v12 - __bfloat162float(__float2bfloat16(v12));
    float r13 = v13 - __bfloat162float(__float2bfloat16(v13));
    lo4.x = pk(r00, r01); lo4.y = pk(r10, r11);
    lo4.z = pk(r02, r03); lo4.w = pk(r12, r13);
    size_t base = (size_t)id * 64 + l;
    xp[base] = hi4;
    xp[base + 32] = lo4;
}

// ---------------- persistent mma.sync RNN --------------------------------
// 128 CTAs x 512 threads (16 warps = wm(4) x wk(4)). CTA tile M64 x N32.
// Warp (wm, wk): full n32, h chunks [wk*16, wk*16+16) + x chunk 64+wk
// (x first, hides cold post-barrier h loads). Epilogue DISTRIBUTED: all
// warps write partials to a 4-slot exchange; warp wk reduces frag f=wk
// (relu/split/store of its 8-byte half-chunk). Same summation order as
// the serial version -> bit-identical results.
__global__ void __launch_bounds__(NTHR, 1) rnn_mma(
    float* __restrict__ out, const float* __restrict__ Wh,
    const float* __restrict__ Wx, const float* __restrict__ Wo,
    const uint4* __restrict__ xp, uint4* __restrict__ hA,
    float* __restrict__ hf)
{
    extern __shared__ __align__(16) uint8_t smem[];
    const int tid = threadIdx.x, l = tid & 31;
    const int wid = tid >> 5;
    const int wm = wid & 3, wk = wid >> 2;
    const int bid = blockIdx.x;
    const int grp = bid >> 5;                  // m-group (4 groups x 32 CTAs)
    const int m0 = grp << 6;
    const int n0 = (bid & 31) << 5;            // hidden tile: 32 x 32
    const uint32_t sB = smem_u32(smem);

    // ---- one-time: pack B slice (rows n0..n0+31 of [Wh | Wx]) into smem ----
    for (int e = tid; e < 32 * 1088; e += NTHR) {
        int nl = e / 1088, k = e - nl * 1088;
        float v = (k < 1024) ? Wh[(size_t)(n0 + nl) * 1024 + k]
                             : Wx[(size_t)(n0 + nl) * 64 + (k - 1024)];
        __nv_bfloat16 h = __float2bfloat16(v);
        __nv_bfloat16 lo = __float2bfloat16(v - __bfloat162float(h));
        int kc = k >> 4, fr = nl >> 3, frp = fr >> 1, f01 = fr & 1;
        int lane = ((nl & 7) << 2) | ((k & 7) >> 1);
        int w = (k >> 3) & 1, hb = k & 1;
        uint32_t off = (uint32_t)kc * 2048 + frp * 512 + lane * 16 + f01 * 8 + w * 4 + hb * 2;
        *reinterpret_cast<__nv_bfloat16*>(smem + off)        = h;
        *reinterpret_cast<__nv_bfloat16*>(smem + off + 1024) = lo;
    }
    // zero h buffer 0 (h_{-1} = 0)
    {
        uint4 z = make_uint4(0, 0, 0, 0);
        for (int i = bid * NTHR + tid; i < HBUF; i += NCTA * NTHR) hA[i] = z;
    }
    grid_sync_all();

    const int mtg   = (m0 >> 4) + wm;          // this warp's global m16 tile
    const int kcd   = (n0 >> 4);               // epilogue dest kc (2 chunks)
    const int kbase = wk * 16;                 // this warp's first h chunk
    const int kcx   = 64 + wk;                 // this warp's x chunk

    for (int t = 0; t < T_; ++t) {
        const uint4* __restrict__ hcur = hA + (size_t)(t & 1) * HBUF;
        uint4* __restrict__ hnxt       = hA + (size_t)((t + 1) & 1) * HBUF;
        const uint4* __restrict__ xpt  = xp + (size_t)t * 4096;

        float chh[4][4], chl_[4][4], clh[4][4];
#pragma unroll
        for (int f = 0; f < 4; ++f)
#pragma unroll
            for (int j = 0; j < 4; ++j)
                chh[f][j] = chl_[f][j] = clh[f][j] = 0.f;

        // ---- prologue: issue first 4 h-A loads, then load + compute x ------
        uint4 sAh[4], sAl[4];
#pragma unroll
        for (int p = 0; p < 4; ++p) {
            const uint4* ap = hcur + ((size_t)(mtg * 64 + kbase + p) * 2) * 32 + l;
            sAh[p] = ap[0];
            sAl[p] = ap[32];
        }
        uint4 xAh, xAl;
        {
            const uint4* ap = xpt + ((size_t)(mtg * 4 + wk) * 2) * 32 + l;
            xAh = ap[0];
            xAl = ap[32];
        }

        auto chunk = [&](int kc, const uint4& Ah, const uint4& Al) {
            const uint32_t ba = sB + (uint32_t)kc * 2048 + l * 16;
            uint32_t bh[8], bl[8];
            lds128(bh,     ba);         lds128(bh + 4, ba + 512);
            lds128(bl,     ba + 1024);  lds128(bl + 4, ba + 1536);
            const uint32_t* ah = reinterpret_cast<const uint32_t*>(&Ah);
            const uint32_t* al = reinterpret_cast<const uint32_t*>(&Al);
            mma16816(chh[0],  ah, bh);      mma16816(chh[1],  ah, bh + 2);
            mma16816(chh[2],  ah, bh + 4);  mma16816(chh[3],  ah, bh + 6);
            mma16816(chl_[0], ah, bl);      mma16816(chl_[1], ah, bl + 2);
            mma16816(chl_[2], ah, bl + 4);  mma16816(chl_[3], ah, bl + 6);
            mma16816(clh[0],  al, bh);      mma16816(clh[1],  al, bh + 2);
            mma16816(clh[2],  al, bh + 4);  mma16816(clh[3],  al, bh + 6);
        };

        // x chunk first: covers the in-flight h-A cold loads
        chunk(kcx, xAh, xAl);

        // ---- 16 h chunks under unroll-4 (slot i&3 static) -------------------
#pragma unroll 4
        for (int i = 0; i < 16; ++i) {
            const int s = i & 3;
            chunk(kbase + i, sAh[s], sAl[s]);
            if (i < 12) {
                const uint4* ap = hcur + ((size_t)(mtg * 64 + kbase + i + 4) * 2) * 32 + l;
                sAh[s] = ap[0];
                sAl[s] = ap[32];
            }
        }

        // ---- distributed combine: every warp writes its 4-frag partials ----
        {
            const uint32_t eo = EXCH_OFF + (uint32_t)wk * 8192 + wm * 2048 + l * 16;
#pragma unroll
            for (int f = 0; f < 4; ++f) {
                float4 s4 = make_float4(
                    chh[f][0] + chl_[f][0] + clh[f][0],
                    chh[f][1] + chl_[f][1] + clh[f][1],
                    chh[f][2] + chl_[f][2] + clh[f][2],
                    chh[f][3] + chl_[f][3] + clh[f][3]);
                *reinterpret_cast<float4*>(smem + eo + f * 512) = s4;
            }
        }
        __syncthreads();
        // warp wk reduces frag f = wk (sum wk0..wk3, same order as before)
        {
            const int f = wk;
            float s0 = 0.f, s1 = 0.f, s2 = 0.f, s3 = 0.f;
#pragma unroll
            for (int q = 0; q < 4; ++q) {
                float4 p = *reinterpret_cast<const float4*>(
                    smem + EXCH_OFF + q * 8192 + wm * 2048 + f * 512 + l * 16);
                s0 += p.x; s1 += p.y; s2 += p.z; s3 += p.w;
            }
            s0 = fmaxf(s0, 0.f); s1 = fmaxf(s1, 0.f);
            s2 = fmaxf(s2, 0.f); s3 = fmaxf(s3, 0.f);
            float r0 = s0 - __bfloat162float(__float2bfloat16(s0));
            float r1 = s1 - __bfloat162float(__float2bfloat16(s1));
            float r2 = s2 - __bfloat162float(__float2bfloat16(s2));
            float r3 = s3 - __bfloat162float(__float2bfloat16(s3));
            uint2 hi2 = make_uint2(pk(s0, s1), pk(s2, s3));
            uint2 lo2 = make_uint2(pk(r0, r1), pk(r2, r3));
            // even frag -> words (x,y) of the uint4; odd frag -> (z,w)
            uint4* dstb = hnxt + ((size_t)(mtg * 64 + kcd + (f >> 1)) * 2) * 32 + l;
            reinterpret_cast<uint2*>(dstb)[f & 1]        = hi2;
            reinterpret_cast<uint2*>(dstb + 32)[f & 1]   = lo2;
            if (t == T_ - 1) {
                int r0w = mtg * 16 + (l >> 2);
                int c0 = n0 + f * 8 + 2 * (l & 3);
                *(float2*)&hf[(size_t)r0w * H_ + c0]       = make_float2(s0, s1);
                *(float2*)&hf[(size_t)(r0w + 8) * H_ + c0] = make_float2(s2, s3);
            }
        }
        group_sync(grp);
    }

    // ---- final: out[m][o] = sum_k h[m][k] * Wo[o][k]; 2 batch rows per CTA ---
    {
        float* sw = (float*)smem;                 // [128][129] padded
        float* sh = (float*)smem + 128 * 129;     // [2][1024]
        const int m = bid * 2;
        const int half = (tid >> 7) & 1, o = tid & 127;
        for (int i = tid; i < 2 * H_; i += NTHR)
            sh[i] = hf[(size_t)(m + (i >> 10)) * H_ + (i & 1023)];
        float acc = 0.f;
        for (int k0 = 0; k0 < H_; k0 += 128) {
            __syncthreads();
            for (int i = tid; i < 128 * 128; i += NTHR) {
                int oo = i >> 7, kk = i & 127;
                sw[oo * 129 + kk] = Wo[(size_t)oo * H_ + k0 + kk];
            }
            __syncthreads();
            if (tid < 256) {
#pragma unroll 8
                for (int kk = 0; kk < 128; ++kk)
                    acc = fmaf(sh[half * H_ + k0 + kk], sw[o * 129 + kk], acc);
            }
        }
        if (tid < 256)
            out[(size_t)(m + half) * OUT_ + o] = acc;
    }
}

// ---------------- launch --------------------------------------------------
extern "C" void kernel_launch(void* const* d_in, const int* in_sizes, int n_in,
                              void* d_out, int out_size) {
    (void)in_sizes; (void)n_in; (void)out_size;
    const float* x  = (const float*)d_in[0];
    const float* Wh = (const float*)d_in[1];
    const float* Wx = (const float*)d_in[2];
    const float* Wo = (const float*)d_in[3];
    float* out = (float*)d_out;

    uint4 *phA, *pxp;
    float* phf;
    cudaGetSymbolAddress((void**)&phA, g_hA);
    cudaGetSymbolAddress((void**)&pxp, g_xp);
    cudaGetSymbolAddress((void**)&phf, g_hf);

    pack_x<<<4096, 256>>>(x, pxp);

    cudaFuncSetAttribute(rnn_mma, cudaFuncAttributeMaxDynamicSharedMemorySize, SMEM_BYTES);
    rnn_mma<<<NCTA, NTHR, SMEM_BYTES>>>(out, Wh, Wx, Wo, pxp, phA, phf);
}